// round 9
// baseline (speedup 1.0000x reference)
#include <cuda_runtime.h>
#include <cuda_fp16.h>
#include <cstdint>

#define NNODES 100000
#define NEDGES 3200000
#define INDIM 256
#define HID 64
#define OUTD 32
#define NSCANB 98   // ceil(100000/1024)

// ---------------- scratch ----------------
__device__ __align__(128) int      g_deg[NNODES];
__device__ __align__(128) float    g_dinv[NNODES];
__device__ __align__(128) int      g_rowptr[NNODES + 1];
__device__ __align__(128) int      g_bsum[NSCANB];
__device__ __align__(128) int      g_epos[NEDGES];                // rank of edge within its dst
__device__ __align__(128) uint64_t g_csr[NEDGES];                 // (norm_bits<<32) | (src*128)
__device__ __align__(128) __half   g_h1[(size_t)NNODES * HID];    // fp16: X@W1
__device__ __align__(128) __half   g_h1r[(size_t)NNODES * HID];   // fp16: relu(agg1)
__device__ __align__(128) __half   g_h2[(size_t)NNODES * OUTD];   // fp16: h1r@W2
__device__ int g_is64;

// ---------------- detect index dtype (1 warp, parallel) ----------------
__global__ void k_detect(const int* __restrict__ ei32) {
    int lane = threadIdx.x;
    int acc = 0;
    for (int k = lane; k < 512; k += 32) {
        acc |= ei32[2 * k + 1];
        acc |= ei32[2 * (NEDGES / 2 + k) + 1];
    }
#pragma unroll
    for (int off = 16; off > 0; off >>= 1) acc |= __shfl_xor_sync(0xffffffffu, acc, off);
    if (lane == 0) g_is64 = (acc == 0) ? 1 : 0;
}

__device__ __forceinline__ void load_edge(const void* ei, int e, int& s, int& d) {
    if (g_is64) {
        const long long* p = (const long long*)ei;
        s = (int)p[e];
        d = (int)p[NEDGES + e];
    } else {
        const int* p = (const int*)ei;
        s = p[e];
        d = p[NEDGES + e];
    }
}

// count in-degree AND record each edge's rank within its dst (atomic return value)
__global__ void k_count(const void* __restrict__ ei) {
    int e = blockIdx.x * blockDim.x + threadIdx.x;
    if (e >= NEDGES) return;
    int s, d;
    load_edge(ei, e, s, d);
    g_epos[e] = atomicAdd(&g_deg[d], 1);
}

// ---------------- scan ----------------
__global__ void k_scan_block() {
    __shared__ int s[1024];
    int t = threadIdx.x;
    int gi = blockIdx.x * 1024 + t;
    int v = (gi < NNODES) ? g_deg[gi] : 0;
    s[t] = v;
    __syncthreads();
#pragma unroll
    for (int off = 1; off < 1024; off <<= 1) {
        int a = (t >= off) ? s[t - off] : 0;
        __syncthreads();
        s[t] += a;
        __syncthreads();
    }
    if (gi <= NNODES) g_rowptr[gi] = s[t] - v;
    if (t == 1023) g_bsum[blockIdx.x] = s[1023];
}

__global__ void k_scan_add() {
    __shared__ int spfx;
    int b = blockIdx.x;
    int t = threadIdx.x;
    if (t < 32) {
        int s = 0;
        for (int i = t; i < b; i += 32) s += g_bsum[i];
#pragma unroll
        for (int off = 16; off > 0; off >>= 1) s += __shfl_xor_sync(0xffffffffu, s, off);
        if (t == 0) spfx = s;
    }
    __syncthreads();
    int i = b * 1024 + t;
    if (i < NNODES) {
        g_rowptr[i] = g_rowptr[i] + spfx;
        g_dinv[i]   = rsqrtf((float)g_deg[i] + 1.0f);
    }
    if (i == 0) g_rowptr[NNODES] = NEDGES;
}

// ---------------- fill CSR (no atomics: pos = rowptr[d] + epos[e]) ----------------
__global__ void k_fill(const void* __restrict__ ei) {
    int e = blockIdx.x * blockDim.x + threadIdx.x;
    if (e >= NEDGES) return;
    int s, d;
    load_edge(ei, e, s, d);
    int pos = g_rowptr[d] + g_epos[e];
    float nrm = g_dinv[s] * g_dinv[d];
    g_csr[pos] = ((uint64_t)__float_as_uint(nrm) << 32) | (uint32_t)(s * 128);
}

// ---------------- HMMA GEMM: Hh[M,NO] = X[M,K] @ W[K,NO] ----------------
// 256 thr = 8 warps (warp owns m16, M-tile 128). K-tiles of 64. SW128-swizzled smem.
#define SWZ(off) ((off) ^ (((off) >> 3) & 0x70))
template <int K, int NO, bool FP32IN>
__global__ void __launch_bounds__(256) k_hmma(const void* __restrict__ Xv,
                                              const float* __restrict__ W,
                                              __half* __restrict__ Hh) {
    __shared__ __align__(16) __half xs[128 * 64];
    __shared__ __align__(16) __half wsm[64 * 64];
    const int tid  = threadIdx.x;
    const int warp = tid >> 5;
    const int lane = tid & 31;
    const int row0 = blockIdx.x * 128;
    constexpr int NB = NO / 8;

    float acc[NB][4];
#pragma unroll
    for (int n = 0; n < NB; n++)
#pragma unroll
        for (int q = 0; q < 4; q++) acc[n][q] = 0.0f;

    uint32_t xs_base  = (uint32_t)__cvta_generic_to_shared(xs);
    uint32_t wsm_base = (uint32_t)__cvta_generic_to_shared(wsm);

    for (int kt = 0; kt < K / 64; kt++) {
        if (FP32IN) {
            const float* X = (const float*)Xv;
            for (int idx = tid; idx < 128 * 32; idx += 256) {
                int row = idx >> 5, cp = idx & 31;
                int gr = row0 + row;
                float2 v = (gr < NNODES)
                    ? *reinterpret_cast<const float2*>(&X[(size_t)gr * K + kt * 64 + cp * 2])
                    : make_float2(0.0f, 0.0f);
                uint32_t off = SWZ((uint32_t)(row * 128 + cp * 4));
                *reinterpret_cast<__half2*>((char*)xs + off) = __floats2half2_rn(v.x, v.y);
            }
        } else {
            const __half* X = (const __half*)Xv;
            for (int idx = tid; idx < 128 * 8; idx += 256) {
                int row = idx >> 3, cp = idx & 7;
                int gr = row0 + row;
                uint4 v = (gr < NNODES)
                    ? *reinterpret_cast<const uint4*>(&X[(size_t)gr * K + kt * 64 + cp * 8])
                    : make_uint4(0, 0, 0, 0);
                uint32_t off = SWZ((uint32_t)(row * 128 + cp * 16));
                *reinterpret_cast<uint4*>((char*)xs + off) = v;
            }
        }
        for (int idx = tid; idx < 64 * (NO / 2); idx += 256) {
            int row = idx / (NO / 2), cp = idx % (NO / 2);
            float2 v = *reinterpret_cast<const float2*>(&W[(size_t)(kt * 64 + row) * NO + cp * 2]);
            uint32_t off = SWZ((uint32_t)(row * 128 + cp * 4));
            *reinterpret_cast<__half2*>((char*)wsm + off) = __floats2half2_rn(v.x, v.y);
        }
        __syncthreads();

#pragma unroll
        for (int ks = 0; ks < 4; ks++) {
            uint32_t a0, a1, a2, a3;
            {
                uint32_t off = (uint32_t)((warp * 16 + (lane & 15)) * 128 + ks * 32 + (lane >> 4) * 16);
                uint32_t addr = xs_base + SWZ(off);
                asm volatile("ldmatrix.sync.aligned.m8n8.x4.shared.b16 {%0,%1,%2,%3}, [%4];"
                             : "=r"(a0), "=r"(a1), "=r"(a2), "=r"(a3) : "r"(addr));
            }
#pragma unroll
            for (int nb2 = 0; nb2 < NO / 16; nb2++) {
                uint32_t b0, b1, b2, b3;
                uint32_t off = (uint32_t)((ks * 16 + (lane & 15)) * 128 + nb2 * 32 + (lane >> 4) * 16);
                uint32_t addr = wsm_base + SWZ(off);
                asm volatile("ldmatrix.sync.aligned.m8n8.x4.trans.shared.b16 {%0,%1,%2,%3}, [%4];"
                             : "=r"(b0), "=r"(b1), "=r"(b2), "=r"(b3) : "r"(addr));
                float* c = acc[2 * nb2];
                asm volatile("mma.sync.aligned.m16n8k16.row.col.f32.f16.f16.f32 "
                             "{%0,%1,%2,%3}, {%4,%5,%6,%7}, {%8,%9}, {%0,%1,%2,%3};"
                             : "+f"(c[0]), "+f"(c[1]), "+f"(c[2]), "+f"(c[3])
                             : "r"(a0), "r"(a1), "r"(a2), "r"(a3), "r"(b0), "r"(b1));
                float* c2 = acc[2 * nb2 + 1];
                asm volatile("mma.sync.aligned.m16n8k16.row.col.f32.f16.f16.f32 "
                             "{%0,%1,%2,%3}, {%4,%5,%6,%7}, {%8,%9}, {%0,%1,%2,%3};"
                             : "+f"(c2[0]), "+f"(c2[1]), "+f"(c2[2]), "+f"(c2[3])
                             : "r"(a0), "r"(a1), "r"(a2), "r"(a3), "r"(b2), "r"(b3));
            }
        }
        __syncthreads();
    }

    int r0 = row0 + warp * 16 + (lane >> 2);
    int c0 = (lane & 3) * 2;
#pragma unroll
    for (int nb = 0; nb < NB; nb++) {
        if (r0 < NNODES)
            *reinterpret_cast<__half2*>(&Hh[(size_t)r0 * NO + nb * 8 + c0]) =
                __floats2half2_rn(acc[nb][0], acc[nb][1]);
        if (r0 + 8 < NNODES)
            *reinterpret_cast<__half2*>(&Hh[(size_t)(r0 + 8) * NO + nb * 8 + c0]) =
                __floats2half2_rn(acc[nb][2], acc[nb][3]);
    }
}

// ---------------- gather aggregation: 2 warps per node, 8-wide batches ----------------
__global__ void __launch_bounds__(256) k_agg1(const float* __restrict__ b1,
                                              __half* __restrict__ h1r) {
    __shared__ float2 spart[4][32];
    int wid  = threadIdx.x >> 5;
    int node = blockIdx.x * 4 + (wid >> 1);
    int half = wid & 1;
    int lane = threadIdx.x & 31;
    int beg = g_rowptr[node], end = g_rowptr[node + 1];
    int mid = (beg + end) >> 1;
    int lo = half ? mid : beg;
    int hi = half ? end : mid;

    const char* h1b = (const char*)g_h1;
    float2 acc = make_float2(0.0f, 0.0f);
    int j = lo;
    for (; j + 8 <= hi; j += 8) {
        uint64_t q[8];
#pragma unroll
        for (int t = 0; t < 8; t++) q[t] = g_csr[j + t];
#pragma unroll
        for (int t = 0; t < 8; t++) {
            float nrm = __uint_as_float((uint32_t)(q[t] >> 32));
            float2 vv = __half22float2(
                *reinterpret_cast<const __half2*>(h1b + (uint32_t)q[t] + lane * 4));
            acc.x = fmaf(nrm, vv.x, acc.x);
            acc.y = fmaf(nrm, vv.y, acc.y);
        }
    }
    for (; j < hi; j++) {
        uint64_t q = g_csr[j];
        float nrm = __uint_as_float((uint32_t)(q >> 32));
        float2 vv = __half22float2(
            *reinterpret_cast<const __half2*>(h1b + (uint32_t)q + lane * 4));
        acc.x = fmaf(nrm, vv.x, acc.x);
        acc.y = fmaf(nrm, vv.y, acc.y);
    }

    if (half) spart[wid >> 1][lane] = acc;
    __syncthreads();
    if (!half) {
        float dn = g_dinv[node];
        float sc = dn * dn;
        float2 hv = __half22float2(
            *reinterpret_cast<const __half2*>(&g_h1[(size_t)node * HID + lane * 2]));
        float2 bv = *reinterpret_cast<const float2*>(&b1[lane * 2]);
        float2 o = spart[wid >> 1][lane];
        acc.x += o.x + fmaf(sc, hv.x, bv.x);
        acc.y += o.y + fmaf(sc, hv.y, bv.y);
        *reinterpret_cast<__half2*>(&h1r[(size_t)node * HID + lane * 2]) =
            __floats2half2_rn(fmaxf(acc.x, 0.0f), fmaxf(acc.y, 0.0f));
    }
}

__global__ void __launch_bounds__(256) k_agg2(const float* __restrict__ b2,
                                              float* __restrict__ out) {
    __shared__ float spart[4][32];
    int wid  = threadIdx.x >> 5;
    int node = blockIdx.x * 4 + (wid >> 1);
    int half = wid & 1;
    int lane = threadIdx.x & 31;
    int beg = g_rowptr[node], end = g_rowptr[node + 1];
    int mid = (beg + end) >> 1;
    int lo = half ? mid : beg;
    int hi = half ? end : mid;

    const char* h2b = (const char*)g_h2;
    float acc = 0.0f;
    int j = lo;
    for (; j + 8 <= hi; j += 8) {
        uint64_t q[8];
#pragma unroll
        for (int t = 0; t < 8; t++) q[t] = g_csr[j + t];
#pragma unroll
        for (int t = 0; t < 8; t++) {
            float nrm = __uint_as_float((uint32_t)(q[t] >> 32));
            float v = __half2float(
                *reinterpret_cast<const __half*>(h2b + (((uint32_t)q[t]) >> 1) + lane * 2));
            acc = fmaf(nrm, v, acc);
        }
    }
    for (; j < hi; j++) {
        uint64_t q = g_csr[j];
        float nrm = __uint_as_float((uint32_t)(q >> 32));
        float v = __half2float(
            *reinterpret_cast<const __half*>(h2b + (((uint32_t)q) >> 1) + lane * 2));
        acc = fmaf(nrm, v, acc);
    }

    if (half) spart[wid >> 1][lane] = acc;
    __syncthreads();
    if (!half) {
        float dn = g_dinv[node];
        acc += spart[wid >> 1][lane];
        acc += fmaf(dn * dn, __half2float(g_h2[(size_t)node * OUTD + lane]), b2[lane]);
        out[(size_t)node * OUTD + lane] = acc;
    }
}

// ---------------- launch ----------------
extern "C" void kernel_launch(void* const* d_in, const int* in_sizes, int n_in,
                              void* d_out, int out_size) {
    const float* x  = (const float*)d_in[0];
    const void*  ei = d_in[1];
    const float* W1 = (const float*)d_in[2];
    const float* b1 = (const float*)d_in[3];
    const float* W2 = (const float*)d_in[4];
    const float* b2 = (const float*)d_in[5];
    float*       out = (float*)d_out;

    void *ph1, *ph1r, *ph2, *pdeg;
    cudaGetSymbolAddress(&ph1,  g_h1);
    cudaGetSymbolAddress(&ph1r, g_h1r);
    cudaGetSymbolAddress(&ph2,  g_h2);
    cudaGetSymbolAddress(&pdeg, g_deg);
    __half* h1  = (__half*)ph1;
    __half* h1r = (__half*)ph1r;
    __half* h2  = (__half*)ph2;

    static cudaStream_t s2 = nullptr;
    static cudaEvent_t evF = nullptr, evJ = nullptr;
    if (s2 == nullptr) {
        cudaStreamCreateWithFlags(&s2, cudaStreamNonBlocking);
        cudaEventCreateWithFlags(&evF, cudaEventDisableTiming);
        cudaEventCreateWithFlags(&evJ, cudaEventDisableTiming);
    }

    const int NT = 256;
    const int EB = (NEDGES + NT - 1) / NT;
    const int GB = (NNODES + 127) / 128;

    // fork: GEMM1 (depends only on x,W1) runs parallel to the CSR build
    cudaEventRecord(evF, 0);
    cudaStreamWaitEvent(s2, evF, 0);
    k_hmma<INDIM, HID, true><<<GB, NT, 0, s2>>>(x, W1, h1);
    cudaEventRecord(evJ, s2);

    // CSR build on the main stream
    k_detect<<<1, 32>>>((const int*)ei);
    cudaMemsetAsync(pdeg, 0, NNODES * sizeof(int));
    k_count<<<EB, NT>>>(ei);
    k_scan_block<<<NSCANB, 1024>>>();
    k_scan_add<<<NSCANB, 1024>>>();
    k_fill<<<EB, NT>>>(ei);

    // join, then layer 1 aggregate + layer 2
    cudaStreamWaitEvent(0, evJ, 0);
    k_agg1<<<NNODES / 4, NT>>>(b1, h1r);
    k_hmma<HID, OUTD, false><<<GB, NT>>>(h1r, W2, h2);
    k_agg2<<<NNODES / 4, NT>>>(b2, out);
}

// round 10
// speedup vs baseline: 1.0985x; 1.0985x over previous
#include <cuda_runtime.h>
#include <cuda_fp16.h>
#include <cstdint>

#define NNODES 100000
#define NEDGES 3200000
#define INDIM 256
#define HID 64
#define OUTD 32
#define NSCANB 98   // ceil(100000/1024)

// ---------------- scratch ----------------
__device__ __align__(128) int      g_deg[NNODES];
__device__ __align__(128) float    g_dinv[NNODES];
__device__ __align__(128) int      g_rowptr[NNODES + 1];
__device__ __align__(128) int      g_cursor[NNODES];
__device__ __align__(128) int      g_bsum[NSCANB];
__device__ __align__(128) uint32_t g_csr[NEDGES];                 // src*128 (byte offset, HID rows)
__device__ __align__(128) __half   g_h1[(size_t)NNODES * HID];    // fp16: dinv .* (X@W1)
__device__ __align__(128) __half   g_h1r[(size_t)NNODES * HID];   // fp16: relu(agg1)
__device__ __align__(128) __half   g_h2[(size_t)NNODES * OUTD];   // fp16: dinv .* (h1r@W2)
__device__ int g_is64;

// ---------------- detect index dtype (1 warp, parallel) ----------------
__global__ void k_detect(const int* __restrict__ ei32) {
    int lane = threadIdx.x;
    int acc = 0;
    for (int k = lane; k < 512; k += 32) {
        acc |= ei32[2 * k + 1];
        acc |= ei32[2 * (NEDGES / 2 + k) + 1];
    }
#pragma unroll
    for (int off = 16; off > 0; off >>= 1) acc |= __shfl_xor_sync(0xffffffffu, acc, off);
    if (lane == 0) g_is64 = (acc == 0) ? 1 : 0;
}

__device__ __forceinline__ void load_edge(const void* ei, int e, int& s, int& d) {
    if (g_is64) {
        const long long* p = (const long long*)ei;
        s = (int)p[e];
        d = (int)p[NEDGES + e];
    } else {
        const int* p = (const int*)ei;
        s = p[e];
        d = p[NEDGES + e];
    }
}

__global__ void k_count(const void* __restrict__ ei) {
    int e = blockIdx.x * blockDim.x + threadIdx.x;
    if (e >= NEDGES) return;
    int s, d;
    load_edge(ei, e, s, d);
    atomicAdd(&g_deg[d], 1);
}

// dinv right after count (GEMM epilogues only need this, not the scan)
__global__ void k_dinv() {
    int i = blockIdx.x * blockDim.x + threadIdx.x;
    if (i < NNODES) g_dinv[i] = rsqrtf((float)g_deg[i] + 1.0f);
}

// ---------------- scan ----------------
__global__ void k_scan_block() {
    __shared__ int s[1024];
    int t = threadIdx.x;
    int gi = blockIdx.x * 1024 + t;
    int v = (gi < NNODES) ? g_deg[gi] : 0;
    s[t] = v;
    __syncthreads();
#pragma unroll
    for (int off = 1; off < 1024; off <<= 1) {
        int a = (t >= off) ? s[t - off] : 0;
        __syncthreads();
        s[t] += a;
        __syncthreads();
    }
    if (gi <= NNODES) g_rowptr[gi] = s[t] - v;
    if (t == 1023) g_bsum[blockIdx.x] = s[1023];
}

__global__ void k_scan_add() {
    __shared__ int spfx;
    int b = blockIdx.x;
    int t = threadIdx.x;
    if (t < 32) {
        int s = 0;
        for (int i = t; i < b; i += 32) s += g_bsum[i];
#pragma unroll
        for (int off = 16; off > 0; off >>= 1) s += __shfl_xor_sync(0xffffffffu, s, off);
        if (t == 0) spfx = s;
    }
    __syncthreads();
    int i = b * 1024 + t;
    if (i < NNODES) {
        int rp = g_rowptr[i] + spfx;
        g_rowptr[i] = rp;
        g_cursor[i] = rp;
    }
    if (i == 0) g_rowptr[NNODES] = NEDGES;
}

// ---------------- fill CSR: 4-byte src offsets, cursor atomic (R8-proven) ----------------
__global__ void k_fill(const void* __restrict__ ei) {
    int e = blockIdx.x * blockDim.x + threadIdx.x;
    if (e >= NEDGES) return;
    int s, d;
    load_edge(ei, e, s, d);
    int pos = atomicAdd(&g_cursor[d], 1);
    g_csr[pos] = (uint32_t)(s * 128);
}

// ---------------- HMMA GEMM: Hh[row,:] = dinv[row] * (X @ W)[row,:], fp16 out ----------------
#define SWZ(off) ((off) ^ (((off) >> 3) & 0x70))
template <int K, int NO, bool FP32IN>
__global__ void __launch_bounds__(256) k_hmma(const void* __restrict__ Xv,
                                              const float* __restrict__ W,
                                              __half* __restrict__ Hh) {
    __shared__ __align__(16) __half xs[128 * 64];
    __shared__ __align__(16) __half wsm[64 * 64];
    const int tid  = threadIdx.x;
    const int warp = tid >> 5;
    const int lane = tid & 31;
    const int row0 = blockIdx.x * 128;
    constexpr int NB = NO / 8;

    float acc[NB][4];
#pragma unroll
    for (int n = 0; n < NB; n++)
#pragma unroll
        for (int q = 0; q < 4; q++) acc[n][q] = 0.0f;

    uint32_t xs_base  = (uint32_t)__cvta_generic_to_shared(xs);
    uint32_t wsm_base = (uint32_t)__cvta_generic_to_shared(wsm);

    for (int kt = 0; kt < K / 64; kt++) {
        if (FP32IN) {
            const float* X = (const float*)Xv;
            for (int idx = tid; idx < 128 * 32; idx += 256) {
                int row = idx >> 5, cp = idx & 31;
                int gr = row0 + row;
                float2 v = (gr < NNODES)
                    ? *reinterpret_cast<const float2*>(&X[(size_t)gr * K + kt * 64 + cp * 2])
                    : make_float2(0.0f, 0.0f);
                uint32_t off = SWZ((uint32_t)(row * 128 + cp * 4));
                *reinterpret_cast<__half2*>((char*)xs + off) = __floats2half2_rn(v.x, v.y);
            }
        } else {
            const __half* X = (const __half*)Xv;
            for (int idx = tid; idx < 128 * 8; idx += 256) {
                int row = idx >> 3, cp = idx & 7;
                int gr = row0 + row;
                uint4 v = (gr < NNODES)
                    ? *reinterpret_cast<const uint4*>(&X[(size_t)gr * K + kt * 64 + cp * 8])
                    : make_uint4(0, 0, 0, 0);
                uint32_t off = SWZ((uint32_t)(row * 128 + cp * 16));
                *reinterpret_cast<uint4*>((char*)xs + off) = v;
            }
        }
        for (int idx = tid; idx < 64 * (NO / 2); idx += 256) {
            int row = idx / (NO / 2), cp = idx % (NO / 2);
            float2 v = *reinterpret_cast<const float2*>(&W[(size_t)(kt * 64 + row) * NO + cp * 2]);
            uint32_t off = SWZ((uint32_t)(row * 128 + cp * 4));
            *reinterpret_cast<__half2*>((char*)wsm + off) = __floats2half2_rn(v.x, v.y);
        }
        __syncthreads();

#pragma unroll
        for (int ks = 0; ks < 4; ks++) {
            uint32_t a0, a1, a2, a3;
            {
                uint32_t off = (uint32_t)((warp * 16 + (lane & 15)) * 128 + ks * 32 + (lane >> 4) * 16);
                uint32_t addr = xs_base + SWZ(off);
                asm volatile("ldmatrix.sync.aligned.m8n8.x4.shared.b16 {%0,%1,%2,%3}, [%4];"
                             : "=r"(a0), "=r"(a1), "=r"(a2), "=r"(a3) : "r"(addr));
            }
#pragma unroll
            for (int nb2 = 0; nb2 < NO / 16; nb2++) {
                uint32_t b0, b1, b2, b3;
                uint32_t off = (uint32_t)((ks * 16 + (lane & 15)) * 128 + nb2 * 32 + (lane >> 4) * 16);
                uint32_t addr = wsm_base + SWZ(off);
                asm volatile("ldmatrix.sync.aligned.m8n8.x4.trans.shared.b16 {%0,%1,%2,%3}, [%4];"
                             : "=r"(b0), "=r"(b1), "=r"(b2), "=r"(b3) : "r"(addr));
                float* c = acc[2 * nb2];
                asm volatile("mma.sync.aligned.m16n8k16.row.col.f32.f16.f16.f32 "
                             "{%0,%1,%2,%3}, {%4,%5,%6,%7}, {%8,%9}, {%0,%1,%2,%3};"
                             : "+f"(c[0]), "+f"(c[1]), "+f"(c[2]), "+f"(c[3])
                             : "r"(a0), "r"(a1), "r"(a2), "r"(a3), "r"(b0), "r"(b1));
                float* c2 = acc[2 * nb2 + 1];
                asm volatile("mma.sync.aligned.m16n8k16.row.col.f32.f16.f16.f32 "
                             "{%0,%1,%2,%3}, {%4,%5,%6,%7}, {%8,%9}, {%0,%1,%2,%3};"
                             : "+f"(c2[0]), "+f"(c2[1]), "+f"(c2[2]), "+f"(c2[3])
                             : "r"(a0), "r"(a1), "r"(a2), "r"(a3), "r"(b2), "r"(b3));
            }
        }
        __syncthreads();
    }

    int r0 = row0 + warp * 16 + (lane >> 2);
    int c0 = (lane & 3) * 2;
    float s0 = (r0     < NNODES) ? g_dinv[r0]     : 0.0f;
    float s1 = (r0 + 8 < NNODES) ? g_dinv[r0 + 8] : 0.0f;
#pragma unroll
    for (int nb = 0; nb < NB; nb++) {
        if (r0 < NNODES)
            *reinterpret_cast<__half2*>(&Hh[(size_t)r0 * NO + nb * 8 + c0]) =
                __floats2half2_rn(s0 * acc[nb][0], s0 * acc[nb][1]);
        if (r0 + 8 < NNODES)
            *reinterpret_cast<__half2*>(&Hh[(size_t)(r0 + 8) * NO + nb * 8 + c0]) =
                __floats2half2_rn(s1 * acc[nb][2], s1 * acc[nb][3]);
    }
}

// ---------------- gather aggregation: unweighted sums of pre-scaled rows ----------------
// layer 1: 2 warps/node, lane owns 2 cols. out = relu(dinv[d]*(sum + self) + b).
__global__ void __launch_bounds__(256) k_agg1(const float* __restrict__ b1,
                                              __half* __restrict__ h1r) {
    __shared__ float2 spart[4][32];
    int wid  = threadIdx.x >> 5;
    int node = blockIdx.x * 4 + (wid >> 1);
    int half = wid & 1;
    int lane = threadIdx.x & 31;
    int beg = g_rowptr[node], end = g_rowptr[node + 1];
    int mid = (beg + end) >> 1;
    int lo = half ? mid : beg;
    int hi = half ? end : mid;

    const char* h1b = (const char*)g_h1;
    float2 acc = make_float2(0.0f, 0.0f);
    int j = lo;
    for (; j + 8 <= hi; j += 8) {
        uint32_t q[8];
#pragma unroll
        for (int t = 0; t < 8; t++) q[t] = g_csr[j + t];
#pragma unroll
        for (int t = 0; t < 8; t++) {
            float2 vv = __half22float2(
                *reinterpret_cast<const __half2*>(h1b + q[t] + lane * 4));
            acc.x += vv.x;
            acc.y += vv.y;
        }
    }
    for (; j < hi; j++) {
        uint32_t q = g_csr[j];
        float2 vv = __half22float2(
            *reinterpret_cast<const __half2*>(h1b + q + lane * 4));
        acc.x += vv.x;
        acc.y += vv.y;
    }

    if (half) spart[wid >> 1][lane] = acc;
    __syncthreads();
    if (!half) {
        float dn = g_dinv[node];
        float2 hv = __half22float2(
            *reinterpret_cast<const __half2*>(&g_h1[(size_t)node * HID + lane * 2]));
        float2 bv = *reinterpret_cast<const float2*>(&b1[lane * 2]);
        float2 o = spart[wid >> 1][lane];
        float rx = fmaf(dn, acc.x + o.x + hv.x, bv.x);
        float ry = fmaf(dn, acc.y + o.y + hv.y, bv.y);
        *reinterpret_cast<__half2*>(&h1r[(size_t)node * HID + lane * 2]) =
            __floats2half2_rn(fmaxf(rx, 0.0f), fmaxf(ry, 0.0f));
    }
}

// layer 2: lane owns 1 col. out = dinv[d]*(sum + self) + b.
__global__ void __launch_bounds__(256) k_agg2(const float* __restrict__ b2,
                                              float* __restrict__ out) {
    __shared__ float spart[4][32];
    int wid  = threadIdx.x >> 5;
    int node = blockIdx.x * 4 + (wid >> 1);
    int half = wid & 1;
    int lane = threadIdx.x & 31;
    int beg = g_rowptr[node], end = g_rowptr[node + 1];
    int mid = (beg + end) >> 1;
    int lo = half ? mid : beg;
    int hi = half ? end : mid;

    const char* h2b = (const char*)g_h2;
    float acc = 0.0f;
    int j = lo;
    for (; j + 8 <= hi; j += 8) {
        uint32_t q[8];
#pragma unroll
        for (int t = 0; t < 8; t++) q[t] = g_csr[j + t];
#pragma unroll
        for (int t = 0; t < 8; t++) {
            acc += __half2float(
                *reinterpret_cast<const __half*>(h2b + (q[t] >> 1) + lane * 2));
        }
    }
    for (; j < hi; j++) {
        uint32_t q = g_csr[j];
        acc += __half2float(
            *reinterpret_cast<const __half*>(h2b + (q >> 1) + lane * 2));
    }

    if (half) spart[wid >> 1][lane] = acc;
    __syncthreads();
    if (!half) {
        float dn = g_dinv[node];
        acc += spart[wid >> 1][lane];
        acc += __half2float(g_h2[(size_t)node * OUTD + lane]);
        out[(size_t)node * OUTD + lane] = fmaf(dn, acc, b2[lane]);
    }
}

// ---------------- launch ----------------
extern "C" void kernel_launch(void* const* d_in, const int* in_sizes, int n_in,
                              void* d_out, int out_size) {
    const float* x  = (const float*)d_in[0];
    const void*  ei = d_in[1];
    const float* W1 = (const float*)d_in[2];
    const float* b1 = (const float*)d_in[3];
    const float* W2 = (const float*)d_in[4];
    const float* b2 = (const float*)d_in[5];
    float*       out = (float*)d_out;

    void *ph1, *ph1r, *ph2, *pdeg;
    cudaGetSymbolAddress(&ph1,  g_h1);
    cudaGetSymbolAddress(&ph1r, g_h1r);
    cudaGetSymbolAddress(&ph2,  g_h2);
    cudaGetSymbolAddress(&pdeg, g_deg);
    __half* h1  = (__half*)ph1;
    __half* h1r = (__half*)ph1r;
    __half* h2  = (__half*)ph2;

    static cudaStream_t s2 = nullptr;
    static cudaEvent_t evD = nullptr, evJ = nullptr;
    if (s2 == nullptr) {
        cudaStreamCreateWithFlags(&s2, cudaStreamNonBlocking);
        cudaEventCreateWithFlags(&evD, cudaEventDisableTiming);
        cudaEventCreateWithFlags(&evJ, cudaEventDisableTiming);
    }

    const int NT = 256;
    const int EB = (NEDGES + NT - 1) / NT;
    const int NB = (NNODES + NT - 1) / NT;
    const int GB = (NNODES + 127) / 128;

    // main stream: degree + dinv first (GEMM1 epilogue needs dinv)
    k_detect<<<1, 32>>>((const int*)ei);
    cudaMemsetAsync(pdeg, 0, NNODES * sizeof(int));
    k_count<<<EB, NT>>>(ei);
    k_dinv<<<NB, NT>>>();

    // fork: GEMM1 (x, W1, dinv) overlaps scan + fill
    cudaEventRecord(evD, 0);
    cudaStreamWaitEvent(s2, evD, 0);
    k_hmma<INDIM, HID, true><<<GB, NT, 0, s2>>>(x, W1, h1);
    cudaEventRecord(evJ, s2);

    // CSR build continues on main stream
    k_scan_block<<<NSCANB, 1024>>>();
    k_scan_add<<<NSCANB, 1024>>>();
    k_fill<<<EB, NT>>>(ei);

    // join, then aggregate + layer 2
    cudaStreamWaitEvent(0, evJ, 0);
    k_agg1<<<NNODES / 4, NT>>>(b1, h1r);
    k_hmma<HID, OUTD, false><<<GB, NT>>>(h1r, W2, h2);
    k_agg2<<<NNODES / 4, NT>>>(b2, out);
}

// round 11
// speedup vs baseline: 1.2270x; 1.1170x over previous
#include <cuda_runtime.h>
#include <cuda_fp16.h>
#include <cstdint>

#define NNODES 100000
#define NEDGES 3200000
#define INDIM 256
#define HID 64
#define OUTD 32
#define NSCANB 98   // ceil(100000/1024)

// ---------------- scratch ----------------
__device__ __align__(128) int      g_deg[NNODES];
__device__ __align__(128) float    g_dinv[NNODES];
__device__ __align__(128) int      g_rowptr[NNODES + 1];
__device__ __align__(128) int      g_cursor[NNODES];
__device__ __align__(128) int      g_bsum[NSCANB];
__device__ __align__(128) uint32_t g_csr[NEDGES];                 // src*128 (byte offset, HID rows)
__device__ __align__(128) __half   g_h1[(size_t)NNODES * HID];    // fp16: dinv .* (X@W1)
__device__ __align__(128) __half   g_h1r[(size_t)NNODES * HID];   // fp16: relu(agg1)
__device__ __align__(128) __half   g_h2[(size_t)NNODES * OUTD];   // fp16: dinv .* (h1r@W2)
__device__ int g_is64;

// ---------------- detect index dtype (1 warp, parallel) ----------------
__global__ void k_detect(const int* __restrict__ ei32) {
    int lane = threadIdx.x;
    int acc = 0;
    for (int k = lane; k < 512; k += 32) {
        acc |= ei32[2 * k + 1];
        acc |= ei32[2 * (NEDGES / 2 + k) + 1];
    }
#pragma unroll
    for (int off = 16; off > 0; off >>= 1) acc |= __shfl_xor_sync(0xffffffffu, acc, off);
    if (lane == 0) g_is64 = (acc == 0) ? 1 : 0;
}

__device__ __forceinline__ void load_edge(const void* ei, int e, int& s, int& d) {
    if (g_is64) {
        const long long* p = (const long long*)ei;
        s = (int)p[e];
        d = (int)p[NEDGES + e];
    } else {
        const int* p = (const int*)ei;
        s = p[e];
        d = p[NEDGES + e];
    }
}

__global__ void k_count(const void* __restrict__ ei) {
    int e = blockIdx.x * blockDim.x + threadIdx.x;
    if (e >= NEDGES) return;
    int s, d;
    load_edge(ei, e, s, d);
    atomicAdd(&g_deg[d], 1);
}

__global__ void k_dinv() {
    int i = blockIdx.x * blockDim.x + threadIdx.x;
    if (i < NNODES) g_dinv[i] = rsqrtf((float)g_deg[i] + 1.0f);
}

// ---------------- scan ----------------
__global__ void k_scan_block() {
    __shared__ int s[1024];
    int t = threadIdx.x;
    int gi = blockIdx.x * 1024 + t;
    int v = (gi < NNODES) ? g_deg[gi] : 0;
    s[t] = v;
    __syncthreads();
#pragma unroll
    for (int off = 1; off < 1024; off <<= 1) {
        int a = (t >= off) ? s[t - off] : 0;
        __syncthreads();
        s[t] += a;
        __syncthreads();
    }
    if (gi <= NNODES) g_rowptr[gi] = s[t] - v;
    if (t == 1023) g_bsum[blockIdx.x] = s[1023];
}

__global__ void k_scan_add() {
    __shared__ int spfx;
    int b = blockIdx.x;
    int t = threadIdx.x;
    if (t < 32) {
        int s = 0;
        for (int i = t; i < b; i += 32) s += g_bsum[i];
#pragma unroll
        for (int off = 16; off > 0; off >>= 1) s += __shfl_xor_sync(0xffffffffu, s, off);
        if (t == 0) spfx = s;
    }
    __syncthreads();
    int i = b * 1024 + t;
    if (i < NNODES) {
        int rp = g_rowptr[i] + spfx;
        g_rowptr[i] = rp;
        g_cursor[i] = rp;
    }
    if (i == 0) g_rowptr[NNODES] = NEDGES;
}

// ---------------- fill CSR ----------------
__global__ void k_fill(const void* __restrict__ ei) {
    int e = blockIdx.x * blockDim.x + threadIdx.x;
    if (e >= NEDGES) return;
    int s, d;
    load_edge(ei, e, s, d);
    int pos = atomicAdd(&g_cursor[d], 1);
    g_csr[pos] = (uint32_t)(s * 128);
}

#define SWZ(off) ((off) ^ (((off) >> 3) & 0x70))

// ---------------- GEMM1 (pipelined): g_h1[row,:] = dinv[row]*(X@W1)[row,:] ----------------
// 256 thr, M-tile 128, K=256 in 4 tiles of 64. Dynamic smem 64KB:
//   xs[2] ping-pong X tiles (2 x 16KB), wsm all 4 W tiles (32KB), SW128 swizzled.
// Register-prefetch of tile kt+1 overlaps DRAM latency with tile kt's MMAs.
__global__ void __launch_bounds__(256) k_gemm1(const float* __restrict__ X,
                                               const float* __restrict__ W,
                                               __half* __restrict__ Hh) {
    extern __shared__ char dsm[];
    char* xs  = dsm;            // 2 x 16384 bytes
    char* wsm = dsm + 32768;    // 4 x 8192 bytes
    const int tid  = threadIdx.x;
    const int warp = tid >> 5;
    const int lane = tid & 31;
    const int row0 = blockIdx.x * 128;

    float acc[8][4];
#pragma unroll
    for (int n = 0; n < 8; n++)
#pragma unroll
        for (int q = 0; q < 4; q++) acc[n][q] = 0.0f;

    uint32_t xs_base  = (uint32_t)__cvta_generic_to_shared(xs);
    uint32_t wsm_base = (uint32_t)__cvta_generic_to_shared(wsm);

    uint32_t hv[16];
    // prefetch X tile 0 into regs (16 x LDG.64 + cvt)
#pragma unroll
    for (int i = 0; i < 16; i++) {
        int idx = i * 256 + tid;
        int row = idx >> 5, cp = idx & 31;
        int gr = row0 + row;
        float2 v = (gr < NNODES)
            ? *reinterpret_cast<const float2*>(&X[(size_t)gr * INDIM + cp * 2])
            : make_float2(0.0f, 0.0f);
        __half2 h = __floats2half2_rn(v.x, v.y);
        hv[i] = *reinterpret_cast<uint32_t*>(&h);
    }
    // preload ALL of W (256x64 fp32 -> fp16), 4 tiles
#pragma unroll 4
    for (int idx = tid; idx < 256 * 32; idx += 256) {
        int row = idx >> 5, cp = idx & 31;
        float2 v = *reinterpret_cast<const float2*>(&W[(size_t)row * HID + cp * 2]);
        __half2 h = __floats2half2_rn(v.x, v.y);
        uint32_t off = (uint32_t)((row >> 6) * 8192) + SWZ((uint32_t)((row & 63) * 128 + cp * 4));
        *reinterpret_cast<uint32_t*>(wsm + off) = *reinterpret_cast<uint32_t*>(&h);
    }
    // store X tile 0
#pragma unroll
    for (int i = 0; i < 16; i++) {
        int idx = i * 256 + tid;
        int row = idx >> 5, cp = idx & 31;
        uint32_t off = SWZ((uint32_t)(row * 128 + cp * 4));
        *reinterpret_cast<uint32_t*>(xs + off) = hv[i];
    }
    __syncthreads();

    for (int kt = 0; kt < 4; kt++) {
        // prefetch next X tile while computing this one
        if (kt < 3) {
#pragma unroll
            for (int i = 0; i < 16; i++) {
                int idx = i * 256 + tid;
                int row = idx >> 5, cp = idx & 31;
                int gr = row0 + row;
                float2 v = (gr < NNODES)
                    ? *reinterpret_cast<const float2*>(&X[(size_t)gr * INDIM + (kt + 1) * 64 + cp * 2])
                    : make_float2(0.0f, 0.0f);
                __half2 h = __floats2half2_rn(v.x, v.y);
                hv[i] = *reinterpret_cast<uint32_t*>(&h);
            }
        }
        uint32_t xb = xs_base + (uint32_t)((kt & 1) * 16384);
        uint32_t wb = wsm_base + (uint32_t)(kt * 8192);
#pragma unroll
        for (int ks = 0; ks < 4; ks++) {
            uint32_t a0, a1, a2, a3;
            {
                uint32_t off = (uint32_t)((warp * 16 + (lane & 15)) * 128 + ks * 32 + (lane >> 4) * 16);
                asm volatile("ldmatrix.sync.aligned.m8n8.x4.shared.b16 {%0,%1,%2,%3}, [%4];"
                             : "=r"(a0), "=r"(a1), "=r"(a2), "=r"(a3) : "r"(xb + SWZ(off)));
            }
#pragma unroll
            for (int nb2 = 0; nb2 < 4; nb2++) {
                uint32_t b0, b1, b2, b3;
                uint32_t off = (uint32_t)((ks * 16 + (lane & 15)) * 128 + nb2 * 32 + (lane >> 4) * 16);
                asm volatile("ldmatrix.sync.aligned.m8n8.x4.trans.shared.b16 {%0,%1,%2,%3}, [%4];"
                             : "=r"(b0), "=r"(b1), "=r"(b2), "=r"(b3) : "r"(wb + SWZ(off)));
                float* c = acc[2 * nb2];
                asm volatile("mma.sync.aligned.m16n8k16.row.col.f32.f16.f16.f32 "
                             "{%0,%1,%2,%3}, {%4,%5,%6,%7}, {%8,%9}, {%0,%1,%2,%3};"
                             : "+f"(c[0]), "+f"(c[1]), "+f"(c[2]), "+f"(c[3])
                             : "r"(a0), "r"(a1), "r"(a2), "r"(a3), "r"(b0), "r"(b1));
                float* c2 = acc[2 * nb2 + 1];
                asm volatile("mma.sync.aligned.m16n8k16.row.col.f32.f16.f16.f32 "
                             "{%0,%1,%2,%3}, {%4,%5,%6,%7}, {%8,%9}, {%0,%1,%2,%3};"
                             : "+f"(c2[0]), "+f"(c2[1]), "+f"(c2[2]), "+f"(c2[3])
                             : "r"(a0), "r"(a1), "r"(a2), "r"(a3), "r"(b2), "r"(b3));
            }
        }
        if (kt < 3) {
            // write next tile into the OTHER buffer (disjoint from all current reads);
            // the single sync makes it visible and closes the previous round.
            char* xnext = xs + ((kt + 1) & 1) * 16384;
#pragma unroll
            for (int i = 0; i < 16; i++) {
                int idx = i * 256 + tid;
                int row = idx >> 5, cp = idx & 31;
                uint32_t off = SWZ((uint32_t)(row * 128 + cp * 4));
                *reinterpret_cast<uint32_t*>(xnext + off) = hv[i];
            }
            __syncthreads();
        }
    }

    int r0 = row0 + warp * 16 + (lane >> 2);
    int c0 = (lane & 3) * 2;
    float s0 = (r0     < NNODES) ? g_dinv[r0]     : 0.0f;
    float s1 = (r0 + 8 < NNODES) ? g_dinv[r0 + 8] : 0.0f;
#pragma unroll
    for (int nb = 0; nb < 8; nb++) {
        if (r0 < NNODES)
            *reinterpret_cast<__half2*>(&Hh[(size_t)r0 * HID + nb * 8 + c0]) =
                __floats2half2_rn(s0 * acc[nb][0], s0 * acc[nb][1]);
        if (r0 + 8 < NNODES)
            *reinterpret_cast<__half2*>(&Hh[(size_t)(r0 + 8) * HID + nb * 8 + c0]) =
                __floats2half2_rn(s1 * acc[nb][2], s1 * acc[nb][3]);
    }
}

// ---------------- GEMM2 (R10-proven): fp16 in, K=64, N=32 ----------------
__global__ void __launch_bounds__(256) k_gemm2(const __half* __restrict__ X,
                                               const float* __restrict__ W,
                                               __half* __restrict__ Hh) {
    __shared__ __align__(16) __half xs[128 * 64];
    __shared__ __align__(16) __half wsm[64 * 64];
    const int tid  = threadIdx.x;
    const int warp = tid >> 5;
    const int lane = tid & 31;
    const int row0 = blockIdx.x * 128;

    float acc[4][4];
#pragma unroll
    for (int n = 0; n < 4; n++)
#pragma unroll
        for (int q = 0; q < 4; q++) acc[n][q] = 0.0f;

    uint32_t xs_base  = (uint32_t)__cvta_generic_to_shared(xs);
    uint32_t wsm_base = (uint32_t)__cvta_generic_to_shared(wsm);

    for (int idx = tid; idx < 128 * 8; idx += 256) {
        int row = idx >> 3, cp = idx & 7;
        int gr = row0 + row;
        uint4 v = (gr < NNODES)
            ? *reinterpret_cast<const uint4*>(&X[(size_t)gr * HID + cp * 8])
            : make_uint4(0, 0, 0, 0);
        uint32_t off = SWZ((uint32_t)(row * 128 + cp * 16));
        *reinterpret_cast<uint4*>((char*)xs + off) = v;
    }
    for (int idx = tid; idx < 64 * 16; idx += 256) {
        int row = idx >> 4, cp = idx & 15;
        float2 v = *reinterpret_cast<const float2*>(&W[(size_t)row * OUTD + cp * 2]);
        uint32_t off = SWZ((uint32_t)(row * 128 + cp * 4));
        __half2 h = __floats2half2_rn(v.x, v.y);
        *reinterpret_cast<__half2*>((char*)wsm + off) = h;
    }
    __syncthreads();

#pragma unroll
    for (int ks = 0; ks < 4; ks++) {
        uint32_t a0, a1, a2, a3;
        {
            uint32_t off = (uint32_t)((warp * 16 + (lane & 15)) * 128 + ks * 32 + (lane >> 4) * 16);
            asm volatile("ldmatrix.sync.aligned.m8n8.x4.shared.b16 {%0,%1,%2,%3}, [%4];"
                         : "=r"(a0), "=r"(a1), "=r"(a2), "=r"(a3) : "r"(xs_base + SWZ(off)));
        }
#pragma unroll
        for (int nb2 = 0; nb2 < 2; nb2++) {
            uint32_t b0, b1, b2, b3;
            uint32_t off = (uint32_t)((ks * 16 + (lane & 15)) * 128 + nb2 * 32 + (lane >> 4) * 16);
            asm volatile("ldmatrix.sync.aligned.m8n8.x4.trans.shared.b16 {%0,%1,%2,%3}, [%4];"
                         : "=r"(b0), "=r"(b1), "=r"(b2), "=r"(b3) : "r"(wsm_base + SWZ(off)));
            float* c = acc[2 * nb2];
            asm volatile("mma.sync.aligned.m16n8k16.row.col.f32.f16.f16.f32 "
                         "{%0,%1,%2,%3}, {%4,%5,%6,%7}, {%8,%9}, {%0,%1,%2,%3};"
                         : "+f"(c[0]), "+f"(c[1]), "+f"(c[2]), "+f"(c[3])
                         : "r"(a0), "r"(a1), "r"(a2), "r"(a3), "r"(b0), "r"(b1));
            float* c2 = acc[2 * nb2 + 1];
            asm volatile("mma.sync.aligned.m16n8k16.row.col.f32.f16.f16.f32 "
                         "{%0,%1,%2,%3}, {%4,%5,%6,%7}, {%8,%9}, {%0,%1,%2,%3};"
                         : "+f"(c2[0]), "+f"(c2[1]), "+f"(c2[2]), "+f"(c2[3])
                         : "r"(a0), "r"(a1), "r"(a2), "r"(a3), "r"(b2), "r"(b3));
        }
    }

    int r0 = row0 + warp * 16 + (lane >> 2);
    int c0 = (lane & 3) * 2;
    float s0 = (r0     < NNODES) ? g_dinv[r0]     : 0.0f;
    float s1 = (r0 + 8 < NNODES) ? g_dinv[r0 + 8] : 0.0f;
#pragma unroll
    for (int nb = 0; nb < 4; nb++) {
        if (r0 < NNODES)
            *reinterpret_cast<__half2*>(&Hh[(size_t)r0 * OUTD + nb * 8 + c0]) =
                __floats2half2_rn(s0 * acc[nb][0], s0 * acc[nb][1]);
        if (r0 + 8 < NNODES)
            *reinterpret_cast<__half2*>(&Hh[(size_t)(r0 + 8) * OUTD + nb * 8 + c0]) =
                __floats2half2_rn(s1 * acc[nb][2], s1 * acc[nb][3]);
    }
}

// ---------------- gather aggregation (R10-proven) ----------------
__global__ void __launch_bounds__(256) k_agg1(const float* __restrict__ b1,
                                              __half* __restrict__ h1r) {
    __shared__ float2 spart[4][32];
    int wid  = threadIdx.x >> 5;
    int node = blockIdx.x * 4 + (wid >> 1);
    int half = wid & 1;
    int lane = threadIdx.x & 31;
    int beg = g_rowptr[node], end = g_rowptr[node + 1];
    int mid = (beg + end) >> 1;
    int lo = half ? mid : beg;
    int hi = half ? end : mid;

    const char* h1b = (const char*)g_h1;
    float2 acc = make_float2(0.0f, 0.0f);
    int j = lo;
    for (; j + 8 <= hi; j += 8) {
        uint32_t q[8];
#pragma unroll
        for (int t = 0; t < 8; t++) q[t] = g_csr[j + t];
#pragma unroll
        for (int t = 0; t < 8; t++) {
            float2 vv = __half22float2(
                *reinterpret_cast<const __half2*>(h1b + q[t] + lane * 4));
            acc.x += vv.x;
            acc.y += vv.y;
        }
    }
    for (; j < hi; j++) {
        uint32_t q = g_csr[j];
        float2 vv = __half22float2(
            *reinterpret_cast<const __half2*>(h1b + q + lane * 4));
        acc.x += vv.x;
        acc.y += vv.y;
    }

    if (half) spart[wid >> 1][lane] = acc;
    __syncthreads();
    if (!half) {
        float dn = g_dinv[node];
        float2 hv = __half22float2(
            *reinterpret_cast<const __half2*>(&g_h1[(size_t)node * HID + lane * 2]));
        float2 bv = *reinterpret_cast<const float2*>(&b1[lane * 2]);
        float2 o = spart[wid >> 1][lane];
        float rx = fmaf(dn, acc.x + o.x + hv.x, bv.x);
        float ry = fmaf(dn, acc.y + o.y + hv.y, bv.y);
        *reinterpret_cast<__half2*>(&h1r[(size_t)node * HID + lane * 2]) =
            __floats2half2_rn(fmaxf(rx, 0.0f), fmaxf(ry, 0.0f));
    }
}

__global__ void __launch_bounds__(256) k_agg2(const float* __restrict__ b2,
                                              float* __restrict__ out) {
    __shared__ float spart[4][32];
    int wid  = threadIdx.x >> 5;
    int node = blockIdx.x * 4 + (wid >> 1);
    int half = wid & 1;
    int lane = threadIdx.x & 31;
    int beg = g_rowptr[node], end = g_rowptr[node + 1];
    int mid = (beg + end) >> 1;
    int lo = half ? mid : beg;
    int hi = half ? end : mid;

    const char* h2b = (const char*)g_h2;
    float acc = 0.0f;
    int j = lo;
    for (; j + 8 <= hi; j += 8) {
        uint32_t q[8];
#pragma unroll
        for (int t = 0; t < 8; t++) q[t] = g_csr[j + t];
#pragma unroll
        for (int t = 0; t < 8; t++) {
            acc += __half2float(
                *reinterpret_cast<const __half*>(h2b + (q[t] >> 1) + lane * 2));
        }
    }
    for (; j < hi; j++) {
        uint32_t q = g_csr[j];
        acc += __half2float(
            *reinterpret_cast<const __half*>(h2b + (q >> 1) + lane * 2));
    }

    if (half) spart[wid >> 1][lane] = acc;
    __syncthreads();
    if (!half) {
        float dn = g_dinv[node];
        acc += spart[wid >> 1][lane];
        acc += __half2float(g_h2[(size_t)node * OUTD + lane]);
        out[(size_t)node * OUTD + lane] = fmaf(dn, acc, b2[lane]);
    }
}

// ---------------- launch ----------------
extern "C" void kernel_launch(void* const* d_in, const int* in_sizes, int n_in,
                              void* d_out, int out_size) {
    const float* x  = (const float*)d_in[0];
    const void*  ei = d_in[1];
    const float* W1 = (const float*)d_in[2];
    const float* b1 = (const float*)d_in[3];
    const float* W2 = (const float*)d_in[4];
    const float* b2 = (const float*)d_in[5];
    float*       out = (float*)d_out;

    void *ph1, *ph1r, *ph2, *pdeg;
    cudaGetSymbolAddress(&ph1,  g_h1);
    cudaGetSymbolAddress(&ph1r, g_h1r);
    cudaGetSymbolAddress(&ph2,  g_h2);
    cudaGetSymbolAddress(&pdeg, g_deg);
    __half* h1  = (__half*)ph1;
    __half* h1r = (__half*)ph1r;
    __half* h2  = (__half*)ph2;

    static cudaStream_t s2 = nullptr;
    static cudaEvent_t evD = nullptr, evJ = nullptr;
    if (s2 == nullptr) {
        cudaStreamCreateWithFlags(&s2, cudaStreamNonBlocking);
        cudaEventCreateWithFlags(&evD, cudaEventDisableTiming);
        cudaEventCreateWithFlags(&evJ, cudaEventDisableTiming);
        cudaFuncSetAttribute(k_gemm1, cudaFuncAttributeMaxDynamicSharedMemorySize, 65536);
    }

    const int NT = 256;
    const int EB = (NEDGES + NT - 1) / NT;
    const int NB = (NNODES + NT - 1) / NT;
    const int GB = (NNODES + 127) / 128;

    // main stream: degree + dinv first (GEMM epilogues need dinv)
    k_detect<<<1, 32>>>((const int*)ei);
    cudaMemsetAsync(pdeg, 0, NNODES * sizeof(int));
    k_count<<<EB, NT>>>(ei);
    k_dinv<<<NB, NT>>>();

    // fork: GEMM1 overlaps scan + fill
    cudaEventRecord(evD, 0);
    cudaStreamWaitEvent(s2, evD, 0);
    k_gemm1<<<GB, NT, 65536, s2>>>(x, W1, h1);
    cudaEventRecord(evJ, s2);

    // CSR build continues on main stream
    k_scan_block<<<NSCANB, 1024>>>();
    k_scan_add<<<NSCANB, 1024>>>();
    k_fill<<<EB, NT>>>(ei);

    // join, then aggregate + layer 2
    cudaStreamWaitEvent(0, evJ, 0);
    k_agg1<<<NNODES / 4, NT>>>(b1, h1r);
    k_gemm2<<<GB, NT>>>(h1r, W2, h2);
    k_agg2<<<NNODES / 4, NT>>>(b2, out);
}